// round 17
// baseline (speedup 1.0000x reference)
#include <cuda_runtime.h>
#include <cuda_bf16.h>

namespace {
constexpr int B = 512, S = 96, N = 64, H = 512, E = 512;
constexpr int NE = E + N;
constexpr int NTHREADS = 256;
constexpr int KC = 192;                   // conv im2col K

// ---- byte-offset shared memory layout ----
constexpr int SRC_B  = 0;                 // u16[576]
constexpr int DST_B  = 1152;              // u16[576]
constexpr int EID_B  = 2304;              // u16[576]
constexpr int DEG_B  = 3456;              // int[64]
constexpr int OFF_B  = 3712;              // int[65]
constexpr int CNT_B  = 3972;              // int[64]
constexpr int DINV_B = 4228;              // float[64]
constexpr int XT_B   = 4496;              // float[64][98] (16B aligned)
constexpr int XT_LD  = 98;
constexpr int U0_B   = XT_B + 64 * XT_LD * 4;     // 29584

// GEMM-phase view
constexpr int AG_LD   = 104;
constexpr int XAGG_HI_B = U0_B;                        // 29584
constexpr int XAGG_LO_B = XAGG_HI_B + N * AG_LD * 2;   // 42896
constexpr int H1_LD   = 72;
constexpr int H1_HI_B = XAGG_LO_B + N * AG_LD * 2;     // 56208
constexpr int H1_LO_B = H1_HI_B + N * H1_LD * 2;       // 65424, end 74640

// conv-phase view: fragment-packed interleaved, overlays from byte 0
// [s-tile(12)][kc(12)][lane(32)] x 16B {bh0,bh1,bl0,bl1}
constexpr int CONV_BYTES = 12 * 12 * 32 * 16;          // 73728

constexpr int SMEM_BYTES = 74640;                      // 72.9 KB -> 3 CTAs/SM

static_assert(XAGG_HI_B % 16 == 0 && XAGG_LO_B % 16 == 0, "ag align");
static_assert(H1_HI_B % 16 == 0 && H1_LO_B % 16 == 0, "h1 align");
static_assert(CONV_BYTES <= SMEM_BYTES, "conv fits");

// fragment array sizes (unsigned words)
constexpr int F1_WORDS = 64 * 6 * 32 * 2;
constexpr int F2_WORDS = 12 * 32 * 32 * 2;
constexpr int FC_WORDS = 32 * 12 * 32 * 4;
}

// ---- device scratch (static; no allocations) ----
__device__ unsigned g_f1hi[F1_WORDS], g_f1lo[F1_WORDS];
__device__ unsigned g_f2hi[F2_WORDS], g_f2lo[F2_WORDS];
__device__ unsigned g_fchi[FC_WORDS], g_fclo[FC_WORDS];

// ---- helpers ----
__device__ __forceinline__ unsigned smem_u32_of(const void* p) {
    unsigned a;
    asm("{ .reg .u64 t; cvta.to.shared.u64 t, %1; cvt.u32.u64 %0, t; }"
        : "=r"(a) : "l"(p));
    return a;
}
__device__ __forceinline__ void ldsm_x4(unsigned* r, unsigned saddr) {
    asm volatile("ldmatrix.sync.aligned.m8n8.x4.shared.b16 {%0,%1,%2,%3}, [%4];"
                 : "=r"(r[0]), "=r"(r[1]), "=r"(r[2]), "=r"(r[3]) : "r"(saddr));
}
__device__ __forceinline__ void mma16816(float* c, const unsigned* a,
                                         unsigned b0, unsigned b1) {
    asm volatile(
        "mma.sync.aligned.m16n8k16.row.col.f32.bf16.bf16.f32 "
        "{%0,%1,%2,%3}, {%4,%5,%6,%7}, {%8,%9}, {%0,%1,%2,%3};"
        : "+f"(c[0]), "+f"(c[1]), "+f"(c[2]), "+f"(c[3])
        : "r"(a[0]), "r"(a[1]), "r"(a[2]), "r"(a[3]), "r"(b0), "r"(b1));
}
__device__ __forceinline__ unsigned pack_bf2(__nv_bfloat16 lo, __nv_bfloat16 hi) {
    __nv_bfloat162 p(lo, hi);
    return *reinterpret_cast<unsigned*>(&p);
}
__device__ __forceinline__ void split_pair(float v0, float v1,
                                           unsigned& whi, unsigned& wlo) {
    __nv_bfloat16 h0 = __float2bfloat16(v0), h1 = __float2bfloat16(v1);
    __nv_bfloat16 l0 = __float2bfloat16(v0 - __bfloat162float(h0));
    __nv_bfloat16 l1 = __float2bfloat16(v1 - __bfloat162float(h1));
    whi = pack_bf2(h0, h1);
    wlo = pack_bf2(l0, l1);
}

// ================= kernel0: prepack weights into mma-fragment order =================
__global__ void weights_prepack_kernel(const float* __restrict__ W1,
                                       const float* __restrict__ W2,
                                       const float* __restrict__ cw) {
    int idx = blockIdx.x * blockDim.x + threadIdx.x;
    if (idx < F1_WORDS) {
        int T = idx / 384, r = idx % 384;
        int kk = r / 64, r2 = r % 64;
        int lane = r2 >> 1, b = r2 & 1;
        int n = T * 8 + (lane >> 2);
        int k = kk * 16 + 2 * (lane & 3) + b * 8;
        split_pair(W1[(size_t)n * S + k], W1[(size_t)n * S + k + 1],
                   g_f1hi[idx], g_f1lo[idx]);
        return;
    }
    int i2 = idx - F1_WORDS;
    if (i2 < F2_WORDS) {
        int T2 = i2 / 2048, r = i2 % 2048;
        int kg = r / 64, r2 = r % 64;
        int lane = r2 >> 1, b = r2 & 1;
        int s = T2 * 8 + (lane >> 2);
        int k = kg * 16 + 2 * (lane & 3) + b * 8;
        split_pair(W2[(size_t)s * H + k], W2[(size_t)s * H + k + 1],
                   g_f2hi[i2], g_f2lo[i2]);
        return;
    }
    int i3 = i2 - F2_WORDS;
    if (i3 < FC_WORDS) {
        int mt = i3 / 1536, r = i3 % 1536;
        int kc = r / 128, r2 = r % 128;
        int lane = r2 >> 2, q = r2 & 3;
        int row = mt * 16 + (lane >> 2) + (q & 1) * 8;
        int col = kc * 16 + 2 * (lane & 3) + (q >> 1) * 8;
        split_pair(cw[(size_t)row * KC + col], cw[(size_t)row * KC + col + 1],
                   g_fchi[i3], g_fclo[i3]);
    }
}

// ================= fused kernel =================
__global__ __launch_bounds__(NTHREADS, 3)
void gcn_fused_kernel(const float* __restrict__ x,
                      const int*   __restrict__ edge_index,
                      const float* __restrict__ b1,
                      const float* __restrict__ b2,
                      float*       __restrict__ out)
{
    extern __shared__ char smc[];
    unsigned short* s_src = (unsigned short*)(smc + SRC_B);
    unsigned short* s_dst = (unsigned short*)(smc + DST_B);
    unsigned short* s_eid = (unsigned short*)(smc + EID_B);
    int*   s_deg  = (int*)(smc + DEG_B);
    int*   s_off  = (int*)(smc + OFF_B);
    int*   s_cnt  = (int*)(smc + CNT_B);
    float* s_dinv = (float*)(smc + DINV_B);
    float* s_xT   = (float*)(smc + XT_B);   // [64][98]; x^T, later t2

    const int tid = threadIdx.x;
    const int bid = blockIdx.x;

    // ---------- Phase 0: edges, x^T, degrees, CSR ----------
    const int* ei = edge_index + (size_t)bid * 2 * E;
    for (int i = tid; i < E; i += NTHREADS) {
        s_src[i] = (unsigned short)ei[i];
        s_dst[i] = (unsigned short)ei[E + i];
    }
    if (tid < N) {
        s_src[E + tid] = (unsigned short)tid;
        s_dst[E + tid] = (unsigned short)tid;
        s_deg[tid] = 0;
        s_cnt[tid] = 0;
    }
    const float* xb = x + (size_t)bid * S * N;
    for (int i = tid; i < S * N; i += NTHREADS) {
        int s = i >> 6, n = i & 63;
        s_xT[n * XT_LD + s] = xb[i];
    }
    __syncthreads();

    for (int i = tid; i < NE; i += NTHREADS) atomicAdd(&s_deg[s_dst[i]], 1);
    __syncthreads();
    if (tid < N) s_dinv[tid] = rsqrtf((float)s_deg[tid]);
    if (tid == 0) {
        int acc = 0;
        for (int n = 0; n < N; n++) { s_off[n] = acc; acc += s_deg[n]; }
        s_off[N] = acc;
    }
    __syncthreads();
    for (int i = tid; i < NE; i += NTHREADS) {
        int d = s_dst[i];
        int pos = s_off[d] + atomicAdd(&s_cnt[d], 1);
        s_eid[pos] = (unsigned short)i;
    }
    __syncthreads();

    // ---------- Phase 1: xagg = A_hat * x^T -> bf16 hi/lo ----------
    for (int p = tid; p < N * S; p += NTHREADS) {
        int n = p & 63, s = p >> 6;
        float acc = 0.f;
        const int e0 = s_off[n], e1 = s_off[n + 1];
        for (int q = e0; q < e1; q++) {
            int sr = s_src[s_eid[q]];
            acc += s_dinv[sr] * s_xT[sr * XT_LD + s];
        }
        float v = acc * s_dinv[n];
        __nv_bfloat16 hv = __float2bfloat16(v);
        __nv_bfloat16 lv = __float2bfloat16(v - __bfloat162float(hv));
        *(__nv_bfloat16*)(smc + XAGG_HI_B + (n * AG_LD + s) * 2) = hv;
        *(__nv_bfloat16*)(smc + XAGG_LO_B + (n * AG_LD + s) * 2) = lv;
    }
    __syncthreads();

    // ---------- Phases 2+3: mma GEMM1 (relu) + GEMM2, 64-wide H tiles ----------
    const int lane = tid & 31;
    const int wid  = tid >> 5;
    const int gid  = lane >> 2;
    const int tig  = lane & 3;
    const int wr   = wid & 3;       // warp row (m)
    const int wc   = wid >> 2;      // warp col (n)
    const int m0   = 16 * wr;

    const unsigned sbase   = smem_u32_of(smc);
    const unsigned ag_hi_s = sbase + XAGG_HI_B;
    const unsigned ag_lo_s = sbase + XAGG_LO_B;
    const unsigned h1_hi_s = sbase + H1_HI_B;
    const unsigned h1_lo_s = sbase + H1_LO_B;
    const unsigned arow16  = (unsigned)(m0 + (lane & 15));
    const unsigned asel16  = (unsigned)((lane >> 4) * 16);

    float t2acc[6][4];
    #pragma unroll
    for (int nt = 0; nt < 6; nt++)
        #pragma unroll
        for (int q = 0; q < 4; q++) t2acc[nt][q] = 0.f;

    #pragma unroll 1
    for (int ht = 0; ht < 8; ht++) {
        // --- GEMM1: h1 tile [64 m][64 n] ---
        float acc1[4][4];
        #pragma unroll
        for (int nt = 0; nt < 4; nt++)
            #pragma unroll
            for (int q = 0; q < 4; q++) acc1[nt][q] = 0.f;

        for (int kk = 0; kk < 6; kk++) {
            unsigned ah[4], al[4];
            unsigned aoff = arow16 * (AG_LD * 2) + kk * 32 + asel16;
            ldsm_x4(ah, ag_hi_s + aoff);
            ldsm_x4(al, ag_lo_s + aoff);
            #pragma unroll
            for (int nt = 0; nt < 4; nt++) {
                int T = ht * 8 + wc * 4 + nt;
                int fo = ((T * 6 + kk) * 32 + lane) * 2;
                uint2 bh = *(const uint2*)&g_f1hi[fo];
                uint2 bl = *(const uint2*)&g_f1lo[fo];
                mma16816(acc1[nt], ah, bh.x, bh.y);
                mma16816(acc1[nt], ah, bl.x, bl.y);
                mma16816(acc1[nt], al, bh.x, bh.y);
            }
        }
        // bias + relu + bf16 split -> h1 tile smem
        #pragma unroll
        for (int nt = 0; nt < 4; nt++) {
            int hc = ht * 64 + wc * 32 + nt * 8 + 2 * tig;
            int lc = wc * 32 + nt * 8 + 2 * tig;
            float bv0 = b1[hc], bv1 = b1[hc + 1];
            float v0 = fmaxf(acc1[nt][0] + bv0, 0.f);
            float v1 = fmaxf(acc1[nt][1] + bv1, 0.f);
            float v2 = fmaxf(acc1[nt][2] + bv0, 0.f);
            float v3 = fmaxf(acc1[nt][3] + bv1, 0.f);
            unsigned ra = (m0 + gid) * (H1_LD * 2) + lc * 2;
            unsigned rb = (m0 + gid + 8) * (H1_LD * 2) + lc * 2;
            unsigned whi, wlo;
            split_pair(v0, v1, whi, wlo);
            *(unsigned*)(smc + H1_HI_B + ra) = whi;
            *(unsigned*)(smc + H1_LO_B + ra) = wlo;
            split_pair(v2, v3, whi, wlo);
            *(unsigned*)(smc + H1_HI_B + rb) = whi;
            *(unsigned*)(smc + H1_LO_B + rb) = wlo;
        }
        __syncthreads();

        // --- GEMM2 accumulate: t2 += h1_tile @ W2_tile^T ---
        for (int kk = 0; kk < 4; kk++) {
            unsigned ah[4], al[4];
            unsigned aoff = arow16 * (H1_LD * 2) + kk * 32 + asel16;
            ldsm_x4(ah, h1_hi_s + aoff);
            ldsm_x4(al, h1_lo_s + aoff);
            int kg = ht * 4 + kk;
            #pragma unroll
            for (int nt = 0; nt < 6; nt++) {
                int T2 = wc * 6 + nt;
                int fo = ((T2 * 32 + kg) * 32 + lane) * 2;
                uint2 bh = *(const uint2*)&g_f2hi[fo];
                uint2 bl = *(const uint2*)&g_f2lo[fo];
                mma16816(t2acc[nt], ah, bh.x, bh.y);
                mma16816(t2acc[nt], ah, bl.x, bl.y);
                mma16816(t2acc[nt], al, bh.x, bh.y);
            }
        }
        __syncthreads();
    }

    // write t2 -> s_xT fp32 [node][s]
    #pragma unroll
    for (int nt = 0; nt < 6; nt++) {
        int n0 = wc * 48 + nt * 8 + 2 * tig;
        s_xT[(m0 + gid) * XT_LD + n0]         = t2acc[nt][0];
        s_xT[(m0 + gid) * XT_LD + n0 + 1]     = t2acc[nt][1];
        s_xT[(m0 + gid + 8) * XT_LD + n0]     = t2acc[nt][2];
        s_xT[(m0 + gid + 8) * XT_LD + n0 + 1] = t2acc[nt][3];
    }
    __syncthreads();

    // ---------- Phase 4: aggregate t2 (+b2), stage in regs ----------
    float vreg[24];
    #pragma unroll 1
    for (int i = 0; i < 24; i++) {
        int p = tid + i * NTHREADS;
        int n = p & 63, t = p >> 6;
        float acc = 0.f;
        const int e0 = s_off[n], e1 = s_off[n + 1];
        for (int q = e0; q < e1; q++) {
            int sr = s_src[s_eid[q]];
            acc += s_dinv[sr] * s_xT[sr * XT_LD + t];
        }
        vreg[i] = acc * s_dinv[n] + b2[t];
    }
    __syncthreads();   // all reads of meta/xT done; conv buffer may overlay

    // scatter into fragment-packed conv B buffer (overlays from byte 0)
    #pragma unroll 1
    for (int i = 0; i < 24; i++) {
        int p = tid + i * NTHREADS;
        int n = p & 63, t = p >> 6;
        float v = vreg[i];
        __nv_bfloat16 hv = __float2bfloat16(v);
        __nv_bfloat16 lv = __float2bfloat16(v - __bfloat162float(hv));
        #pragma unroll
        for (int k = 0; k < 3; k++) {
            int s = t + 1 - k;
            if (s < 0) s += 96;
            if (s >= 96) s -= 96;
            int K = 3 * n + k;
            int T = s >> 3, kc = K >> 4, kp = K & 15;
            int lane2 = ((s & 7) << 2) + ((kp & 7) >> 1);
            int off = ((T * 12 + kc) * 32 + lane2) * 16
                    + ((kp >= 8) ? 4 : 0) + (kp & 1) * 2;
            *(__nv_bfloat16*)(smc + off)     = hv;
            *(__nv_bfloat16*)(smc + off + 8) = lv;
        }
    }
    __syncthreads();

    // ---------- Phase 5: conv as 3-pass bf16 mma ----------
    float* outb = out + (size_t)bid * S * H;
    const int o0 = wid * 64;

    #pragma unroll 1
    for (int mt = 0; mt < 4; mt++) {
        const int m = o0 + mt * 16;
        const int mt32 = wid * 4 + mt;
        #pragma unroll 1
        for (int half = 0; half < 2; half++) {
            float acc[6][4];
            #pragma unroll
            for (int nt = 0; nt < 6; nt++)
                #pragma unroll
                for (int q = 0; q < 4; q++) acc[nt][q] = 0.f;

            for (int kc = 0; kc < 12; kc++) {
                int fo = ((mt32 * 12 + kc) * 32 + lane) * 4;
                uint4 a4h = *(const uint4*)&g_fchi[fo];
                uint4 a4l = *(const uint4*)&g_fclo[fo];
                unsigned ahi[4] = {a4h.x, a4h.y, a4h.z, a4h.w};
                unsigned alo[4] = {a4l.x, a4l.y, a4l.z, a4l.w};

                #pragma unroll
                for (int nt = 0; nt < 6; nt++) {
                    int T = half * 6 + nt;
                    uint4 bq = *(const uint4*)(smc + ((T * 12 + kc) * 32 + lane) * 16);
                    mma16816(acc[nt], ahi, bq.x, bq.y);
                    mma16816(acc[nt], ahi, bq.z, bq.w);
                    mma16816(acc[nt], alo, bq.x, bq.y);
                }
            }

            #pragma unroll
            for (int nt = 0; nt < 6; nt++) {
                const int s0 = (half * 6 + nt) * 8 + 2 * tig;
                const int o  = m + gid;
                outb[(size_t)s0 * H + o]           = acc[nt][0];
                outb[(size_t)(s0 + 1) * H + o]     = acc[nt][1];
                outb[(size_t)s0 * H + o + 8]       = acc[nt][2];
                outb[(size_t)(s0 + 1) * H + o + 8] = acc[nt][3];
            }
        }
    }
}

extern "C" void kernel_launch(void* const* d_in, const int* in_sizes, int n_in,
                              void* d_out, int out_size)
{
    const float* x   = (const float*)d_in[0];
    const int*   ei  = (const int*)  d_in[1];
    const float* W1  = (const float*)d_in[2];
    const float* b1  = (const float*)d_in[3];
    const float* W2  = (const float*)d_in[4];
    const float* b2  = (const float*)d_in[5];
    const float* cw  = (const float*)d_in[6];
    float* out = (float*)d_out;

    int total = F1_WORDS + F2_WORDS + FC_WORDS;
    weights_prepack_kernel<<<(total + 255) / 256, 256>>>(W1, W2, cw);

    cudaFuncSetAttribute(gcn_fused_kernel,
                         cudaFuncAttributeMaxDynamicSharedMemorySize, SMEM_BYTES);
    gcn_fused_kernel<<<B, NTHREADS, SMEM_BYTES>>>(x, ei, b1, b2, out);
}